// round 14
// baseline (speedup 1.0000x reference)
#include <cuda_runtime.h>
#include <cstdint>

namespace {

constexpr int T_ = 128, H_ = 16, N_ = 64, C_ = 256, S_ = 129;
constexpr int NC_ = N_ * C_;
constexpr int NTHR = 544;          // 17 warps/CTA

constexpr float L2E  = 1.4426950408889634f;
constexpr float LN2  = 0.6931471805599453f;
constexpr float MINF = 1.17549435e-38f;        // 2^-126 == FLT_MIN == TINY

__device__ __forceinline__ float ex2f(float x) { float y; asm("ex2.approx.f32 %0, %1;" : "=f"(y) : "f"(x)); return y; }
__device__ __forceinline__ float lg2f(float x) { float y; asm("lg2.approx.f32 %0, %1;" : "=f"(y) : "f"(x)); return y; }

__device__ __forceinline__ uint32_t smem_u32(const void* p) {
    uint32_t a;
    asm("{ .reg .u64 t; cvta.to.shared.u64 t, %1; cvt.u32.u64 %0, t; }" : "=r"(a) : "l"(p));
    return a;
}
__device__ __forceinline__ uint32_t mapa_rank0(uint32_t local) {
    uint32_t r;
    asm("mapa.shared::cluster.u32 %0, %1, 0;" : "=r"(r) : "r"(local));
    return r;
}
__device__ __forceinline__ void st_cl_f32(uint32_t a, float v) {
    asm volatile("st.shared::cluster.f32 [%0], %1;" :: "r"(a), "f"(v));
}
__device__ __forceinline__ uint32_t atom_add_cluster(uint32_t mapped, uint32_t v) {
    uint32_t old;
    asm volatile("atom.relaxed.cluster.shared::cluster.add.u32 %0, [%1], %2;"
                 : "=r"(old) : "r"(mapped), "r"(v) : "memory");
    return old;
}
__device__ __forceinline__ void mbar_init(uint32_t a, unsigned cnt) {
    asm volatile("mbarrier.init.shared.b64 [%0], %1;" :: "r"(a), "r"(cnt) : "memory");
}
__device__ __forceinline__ void mbar_arrive_cluster(uint32_t mapped) {
    asm volatile("mbarrier.arrive.release.cluster.shared::cluster.b64 _, [%0];"
                 :: "r"(mapped) : "memory");
}
__device__ __forceinline__ void mbar_wait0(uint32_t a) {
    uint32_t done;
    asm volatile(
        "{\n\t.reg .pred p;\n\t"
        "mbarrier.try_wait.parity.acquire.cta.shared::cta.b64 p, [%1], 0;\n\t"
        "selp.b32 %0, 1, 0, p;\n\t}"
        : "=r"(done) : "r"(a) : "memory");
    if (!done) {
        asm volatile(
            "{\n\t.reg .pred P1;\n\t"
            "WL_%=:\n\t"
            "mbarrier.try_wait.parity.acquire.cta.shared::cta.b64 P1, [%0], 0, 0x989680;\n\t"
            "@P1 bra.uni WD_%=;\n\t"
            "bra.uni WL_%=;\n\t"
            "WD_%=:\n\t}"
            :: "r"(a) : "memory");
    }
}
__device__ __forceinline__ void cluster_sync() {
    asm volatile("barrier.cluster.arrive.aligned;" ::: "memory");
    asm volatile("barrier.cluster.wait.aligned;" ::: "memory");
}
__device__ __forceinline__ uint32_t ctarank() {
    uint32_t r; asm("mov.u32 %0, %%cluster_ctarank;" : "=r"(r)); return r;
}

// 2-CTA cluster per n, 544 threads/CTA. Rank0: 16 producer warps + consumer
// (warp 16); rank1: 17 producers. Rows are claimed dynamically from a single
// cluster-wide counter (remote smem atomic) for perfect load balance.
// Producers gather only the 65 deduped columns with SORTED column->lane
// assignment (minimal L1tex sector wavefronts), compute linear
// S[t][c] = sum_h 2^(cls+m), write to rank0 smem at original column index,
// release-arrive on group-of-4 mbarriers. Consumer: linear-domain recurrence.
__global__ __launch_bounds__(NTHR, 1) __cluster_dims__(2, 1, 1)
void fused_kernel(
    const float* __restrict__ mask,      // [T,H,N]
    const float* __restrict__ classify,  // [T,H,N,C]
    const int*   __restrict__ targets,   // [N,64]
    const int*   __restrict__ tlen,      // [N]
    float* __restrict__ out)             // [N]
{
    __shared__ float    S_sh[T_][68];    // linear per-column h-sums
    __shared__ uint64_t mbar[T_ / 4];    // one barrier per 4-row group
    __shared__ int      row_ctr;         // rank0's copy is the global queue
    __shared__ int      tgt_sh[64];
    __shared__ int      cc_sh[T_];
    __shared__ float    res_sh[S_];
    __shared__ int      colv_sh[65];     // entry -> column value
    __shared__ int      scol_sh[65];     // rank  -> column value (sorted)
    __shared__ int      sidx_sh[65];     // rank  -> original entry index

    const int n    = blockIdx.x >> 1;
    const int rank = (int)ctarank();
    const int tid  = threadIdx.x;
    const int w    = tid >> 5;
    const int lane = tid & 31;

    if (rank == 0 && tid < T_ / 4) mbar_init(smem_u32(&mbar[tid]), 128);
    if (tid == 0) row_ctr = 0;
    if (tid < 64) tgt_sh[tid] = targets[n * 64 + tid];
    __syncthreads();

    // entry c (0..64): column value (blank=0 for c=0, else targets[c-1])
    if (tid < 65) colv_sh[tid] = (tid == 0) ? 0 : tgt_sh[tid - 1];
    __syncthreads();
    // warp-parallel rank sort (ties broken by index -> rank is a permutation)
    if (tid < 65) {
        const int v = colv_sh[tid];
        int r = 0;
        for (int j = 0; j < 65; ++j) {
            const int u = colv_sh[j];
            r += (u < v) || (u == v && j < tid);
        }
        scol_sh[r] = v;
        sidx_sh[r] = tid;
    }
    __syncthreads();
    cluster_sync();                 // barriers + tables + counter live

    const bool isProd = (rank == 1) || (w < 16);

    if (isProd) {
        // ======================= producer warp =======================
        // sorted assignment: lane -> sorted ranks l and 32+l; lane31 also 64
        const int sc1 = scol_sh[lane],      oi1 = sidx_sh[lane];
        const int sc2 = scol_sh[32 + lane], oi2 = sidx_sh[32 + lane];
        const int sc3 = scol_sh[64],        oi3 = sidx_sh[64];
        const size_t b1 = (size_t)n * C_ + sc1;
        const size_t b2 = (size_t)n * C_ + sc2;
        const size_t b3 = (size_t)n * C_ + sc3;
        const bool   l31 = (lane == 31);
        const uint32_t qaddr = mapa_rank0(smem_u32(&row_ctr));

        for (;;) {
            int t;
            if (lane == 0) t = (int)atom_add_cluster(qaddr, 1u);
            t = __shfl_sync(0xffffffffu, t, 0);
            if (t >= T_) break;

            const float* base = classify + (size_t)t * H_ * NC_;
            const float  m = (lane < 16)
                ? __ldg(&mask[((size_t)t * H_ + lane) * N_ + n]) * L2E : 0.f;

            // issue all gathers up front (full MLP)
            float v1[H_], v2[H_], v3[H_];
#pragma unroll
            for (int h = 0; h < H_; ++h) {
                const size_t ho = (size_t)h * NC_;
                v1[h] = __ldg(base + ho + b1);
                v2[h] = __ldg(base + ho + b2);
            }
            if (l31) {
#pragma unroll
                for (int h = 0; h < H_; ++h) v3[h] = __ldg(base + (size_t)h * NC_ + b3);
            }

            float s1 = 0.f, s2 = 0.f, s3 = 0.f;
#pragma unroll
            for (int h = 0; h < H_; ++h) {
                const float mh = __shfl_sync(0xffffffffu, m, h);
                s1 += ex2f(__fmaf_rn(v1[h], L2E, mh));
                s2 += ex2f(__fmaf_rn(v2[h], L2E, mh));
                if (l31) s3 += ex2f(__fmaf_rn(v3[h], L2E, mh));
            }

            // write linear sums at ORIGINAL column indices into rank0's S_sh
            const uint32_t r0 = mapa_rank0(smem_u32(&S_sh[t][0]));
            st_cl_f32(r0 + 4u * oi1, s1);
            st_cl_f32(r0 + 4u * oi2, s2);
            if (l31) st_cl_f32(r0 + 4u * oi3, s3);
            mbar_arrive_cluster(mapa_rank0(smem_u32(&mbar[t >> 2])));
        }
        return;
    }

    // =================== consumer warp (rank0, w == 16) ===================
    const int NS = (lane == 31) ? 5 : 4;
    const int sB = 4 * lane;

    // cc prefix scan (reachability frontier)
    {
        int c[4], pfx = 0;
#pragma unroll
        for (int i = 0; i < 4; ++i) {
            int u = 4 * lane + i, v = 0;
            if (u >= 2) {
                int sk = 0;
                if ((u & 1) && u >= 3) sk = (tgt_sh[(u - 1) >> 1] != tgt_sh[(u - 3) >> 1]);
                v = sk + 1;
            }
            pfx += v; c[i] = pfx;
        }
        int tot = pfx;
#pragma unroll
        for (int d = 1; d < 32; d <<= 1) {
            int up = __shfl_up_sync(0xffffffffu, tot, d);
            if (lane >= d) tot += up;
        }
        int excl = tot - pfx;
#pragma unroll
        for (int i = 0; i < 4; ++i) {
            int u = 4 * lane + i;
            if (u >= 1) cc_sh[u] = 2 + excl + c[i];
        }
    }
    __syncwarp();

    bool skipb[5];
#pragma unroll
    for (int i = 0; i < 5; ++i) {
        int s = sB + i;
        skipb[i] = (i < NS) && (s & 1) && (s >= 3) &&
                   (tgt_sh[(s - 1) >> 1] != tgt_sh[(s - 3) >> 1]);
    }

    const int cO1 = 2 * lane + 1;   // col of state 4l+1
    const int cO2 = 2 * lane + 2;   // col of state 4l+3

    // linear-domain state: P[i] = 2^np[i]
    float P[5];
#pragma unroll
    for (int i = 0; i < 5; ++i) P[i] = (sB + i < 2) ? 1.f : 0.f;

    float fE = 0.f, fO1 = 0.f, fO2 = 0.f;   // S values of row 127 (final)

    for (int g = 0; g < T_ / 4; ++g) {
        mbar_wait0(smem_u32(&mbar[g]));
        float sE[4], sO1[4], sO2[4];
#pragma unroll
        for (int k = 0; k < 4; ++k) {
            const int r = 4 * g + k;
            sE[k]  = S_sh[r][0];
            sO1[k] = S_sh[r][cO1];
            sO2[k] = S_sh[r][cO2];
        }
#pragma unroll
        for (int k = 0; k < 4; ++k) {
            const int r = 4 * g + k;
            if (r == 127) { fE = sE[k]; fO1 = sO1[k]; fO2 = sO2[k]; break; }
            const int cc_t = cc_sh[r + 1];

            // e = max(P*S, TINY); unreachable -> TINY
            float e[5];
            e[0] = fmaxf(P[0] * sE[k],  MINF);
            e[1] = fmaxf(P[1] * sO1[k], MINF);
            e[2] = fmaxf(P[2] * sE[k],  MINF);
            e[3] = fmaxf(P[3] * sO2[k], MINF);
            e[4] = fmaxf(P[4] * sE[k],  MINF);
#pragma unroll
            for (int i = 0; i < 5; ++i)
                if (sB + i > cc_t) e[i] = MINF;

            const float em1 = __shfl_up_sync(0xffffffffu, e[3], 1);
            const float em2 = __shfl_up_sync(0xffffffffu, e[2], 1);

            float Pn[5];
            Pn[0] = (lane == 0) ? e[0] : e[0] + em1 + (skipb[0] ? em2 : 0.f);
            Pn[1] = e[1] + e[0] + (skipb[1] ? em1 : 0.f);
#pragma unroll
            for (int i = 2; i < 5; ++i)
                Pn[i] = e[i] + e[i - 1] + (skipb[i] ? e[i - 2] : 0.f);
#pragma unroll
            for (int i = 0; i < 5; ++i) P[i] = Pn[i];
        }
    }

    // final: res2[s] = lg2(P[s]) + lg2(S127[col])
    const float lE  = lg2f(fE), lO1 = lg2f(fO1), lO2 = lg2f(fO2);
    res_sh[sB + 0] = lg2f(P[0]) + lE;
    res_sh[sB + 1] = lg2f(P[1]) + lO1;
    res_sh[sB + 2] = lg2f(P[2]) + lE;
    res_sh[sB + 3] = lg2f(P[3]) + lO2;
    if (lane == 31) res_sh[128] = lg2f(P[4]) + lE;
    __syncwarp();

    if (lane == 0) {
        const int   L = 2 * tlen[n] + 1;
        const float x = res_sh[L - 1], y = res_sh[L - 2];
        const float mx = fmaxf(x, y);
        const float l2 = mx + lg2f(ex2f(x - mx) + ex2f(y - mx));
        out[n] = -((LN2 * l2) / (float)tlen[n]);
    }
}

} // anonymous namespace

extern "C" void kernel_launch(void* const* d_in, const int* /*in_sizes*/, int /*n_in*/,
                              void* d_out, int /*out_size*/) {
    const float* mask     = (const float*)d_in[0];
    const float* classify = (const float*)d_in[1];
    const int*   targets  = (const int*)d_in[2];
    // d_in[3] = input_lengths (always T, unused)
    const int*   tlen     = (const int*)d_in[4];

    fused_kernel<<<2 * N_, NTHR>>>(mask, classify, targets, tlen, (float*)d_out);
}